// round 9
// baseline (speedup 1.0000x reference)
#include <cuda_runtime.h>
#include <cstdint>

// Problem constants (fixed by the reference)
#define B_DIM 16
#define S_DIM 4096
#define H_DIM 768
#define NUM_WORDS 2048          // S/2
#define ROW_BYTES (H_DIM * 4)   // 3072 bytes per token/word row
#define NTHR 96                 // threads: each owns a 32B chunk of the row
#define W_PB 4                  // words per block

// One block per (4 contiguous words, batch); grid 512 x 16 = 8192 blocks.
//
// word_ids[b, 1..S-2] is non-decreasing with contiguous values 0..maxw
// (cumsum construction); positions 0 and S-1 are -1 (CLS/SEP, dropped).
// Threads c<=4 binary-search the start token of words w0..w0+4; for w > maxw
// lower_bound == S-1, so absent words get cnt=0 -> zero rows (matches ref).
//
// Each thread owns 32 bytes (two 16B chunks) of every row. The unroll-2 token
// loop issues FOUR independent streaming 16B loads (2 tokens x 2 chunks)
// before any dependent add -> 64B in flight per thread, ~2x round 7, which is
// what the latency model says we need to saturate HBM.
__global__ __launch_bounds__(NTHR) void seg_mean_fused_kernel(
    const char* __restrict__ hs,   // [B, S, H] f32 as bytes
    const int*  __restrict__ wid,  // [B, S]
    char*       __restrict__ out)  // [B, NUM_WORDS, H] f32 as bytes
{
    const int b  = blockIdx.y;
    const int w0 = blockIdx.x * W_PB;
    const int c  = threadIdx.x;

    __shared__ int sm[W_PB + 1];
    if (c <= W_PB) {
        const int* __restrict__ row = wid + (size_t)b * S_DIM;
        const int target = w0 + c;
        int lo = 1, hi = S_DIM - 1;          // search [1, S-1)
        while (lo < hi) {
            int mid = (lo + hi) >> 1;
            if (__ldg(row + mid) < target) lo = mid + 1; else hi = mid;
        }
        sm[c] = lo;
    }
    __syncthreads();

    const char* __restrict__ base =
        hs + (size_t)b * S_DIM * ROW_BYTES + c * 32;
    char* __restrict__ ob =
        out + ((size_t)b * NUM_WORDS + w0) * ROW_BYTES + c * 32;

    int t = sm[0];
    const char* p = base + (long)t * ROW_BYTES;   // running byte pointer

#pragma unroll
    for (int i = 0; i < W_PB; ++i) {
        const int e = sm[i + 1];
        const int cnt = e - t;

        // packed f32x2 accumulators: a0,a1 = chunk0 (16B), a2,a3 = chunk1
        unsigned long long a0 = 0ull, a1 = 0ull, a2 = 0ull, a3 = 0ull;

        // unroll-2 tokens: 4 independent 16B loads in flight per iteration
        while (t + 2 <= e) {
            unsigned long long x0, x1, x2, x3, y0, y1, y2, y3;
            asm volatile("ld.global.cs.v2.u64 {%0,%1}, [%2];"
                         : "=l"(x0), "=l"(x1) : "l"(p));
            asm volatile("ld.global.cs.v2.u64 {%0,%1}, [%2];"
                         : "=l"(x2), "=l"(x3) : "l"(p + 16));
            asm volatile("ld.global.cs.v2.u64 {%0,%1}, [%2];"
                         : "=l"(y0), "=l"(y1) : "l"(p + ROW_BYTES));
            asm volatile("ld.global.cs.v2.u64 {%0,%1}, [%2];"
                         : "=l"(y2), "=l"(y3) : "l"(p + ROW_BYTES + 16));
            asm("add.rn.f32x2 %0, %0, %1;" : "+l"(a0) : "l"(x0));
            asm("add.rn.f32x2 %0, %0, %1;" : "+l"(a1) : "l"(x1));
            asm("add.rn.f32x2 %0, %0, %1;" : "+l"(a2) : "l"(x2));
            asm("add.rn.f32x2 %0, %0, %1;" : "+l"(a3) : "l"(x3));
            asm("add.rn.f32x2 %0, %0, %1;" : "+l"(a0) : "l"(y0));
            asm("add.rn.f32x2 %0, %0, %1;" : "+l"(a1) : "l"(y1));
            asm("add.rn.f32x2 %0, %0, %1;" : "+l"(a2) : "l"(y2));
            asm("add.rn.f32x2 %0, %0, %1;" : "+l"(a3) : "l"(y3));
            p += 2 * ROW_BYTES;
            t += 2;
        }
        if (t < e) {
            unsigned long long x0, x1, x2, x3;
            asm volatile("ld.global.cs.v2.u64 {%0,%1}, [%2];"
                         : "=l"(x0), "=l"(x1) : "l"(p));
            asm volatile("ld.global.cs.v2.u64 {%0,%1}, [%2];"
                         : "=l"(x2), "=l"(x3) : "l"(p + 16));
            asm("add.rn.f32x2 %0, %0, %1;" : "+l"(a0) : "l"(x0));
            asm("add.rn.f32x2 %0, %0, %1;" : "+l"(a1) : "l"(x1));
            asm("add.rn.f32x2 %0, %0, %1;" : "+l"(a2) : "l"(x2));
            asm("add.rn.f32x2 %0, %0, %1;" : "+l"(a3) : "l"(x3));
            p += ROW_BYTES;
            ++t;
        }

        // scale by 1/cnt (0 for empty words) with packed f32x2 muls
        const float inv = (cnt > 0) ? (1.0f / (float)cnt) : 0.0f;
        const unsigned int ib = __float_as_uint(inv);
        const unsigned long long ip =
            ((unsigned long long)ib << 32) | (unsigned long long)ib;
        asm("mul.rn.f32x2 %0, %0, %1;" : "+l"(a0) : "l"(ip));
        asm("mul.rn.f32x2 %0, %0, %1;" : "+l"(a1) : "l"(ip));
        asm("mul.rn.f32x2 %0, %0, %1;" : "+l"(a2) : "l"(ip));
        asm("mul.rn.f32x2 %0, %0, %1;" : "+l"(a3) : "l"(ip));

        char* o = ob + (long)i * ROW_BYTES;
        asm volatile("st.global.cs.v2.u64 [%0], {%1,%2};"
                     :: "l"(o), "l"(a0), "l"(a1) : "memory");
        asm volatile("st.global.cs.v2.u64 [%0], {%1,%2};"
                     :: "l"(o + 16), "l"(a2), "l"(a3) : "memory");
    }
}

extern "C" void kernel_launch(void* const* d_in, const int* in_sizes, int n_in,
                              void* d_out, int out_size)
{
    const char* hs  = (const char*)d_in[0];   // hidden_states [B,S,H] f32
    const int*  wid = (const int*)d_in[1];    // word_ids [B,S] i32
    char*       out = (char*)d_out;           // [B, NUM_WORDS, H] f32

    dim3 grid(NUM_WORDS / W_PB, B_DIM);
    seg_mean_fused_kernel<<<grid, NTHR>>>(hs, wid, out);
}

// round 12
// speedup vs baseline: 1.1706x; 1.1706x over previous
#include <cuda_runtime.h>
#include <cstdint>

// Problem constants (fixed by the reference)
#define B_DIM 16
#define S_DIM 4096
#define H_DIM 768
#define NUM_WORDS 2048            // S/2
#define ROW_BYTES (H_DIM * 4)     // 3072 bytes per token/word row
#define NTHR 192                  // one 16B chunk per thread per row
#define W_PB 8                    // words per block
#define STAGES 6                  // cp.async pipeline depth (per-thread ring)

// One block per (8 contiguous words, batch); grid 512x16... -> 256x16 = 4096.
//
// word_ids[b, 1..S-2] is non-decreasing, contiguous 0..maxw (cumsum);
// positions 0 and S-1 are -1 (CLS/SEP, dropped). Threads c<=8 binary-search
// the start token of words w0..w0+8; for w > maxw lower_bound == S-1, so
// absent words get cnt=0 -> zero rows (matches reference).
//
// The 8 words cover ONE contiguous token range [t0, tEnd). Tokens are
// streamed through a 6-stage per-thread cp.async smem ring: load issue is
// fully decoupled from the accumulate chain, so ~96B/thread stay in flight
// continuously across word boundaries. Stage reuse is same-thread only
// (each thread copies and consumes its own 16B), so no __syncthreads in the
// mainloop. Clamped tail issues target stages that are never consumed and
// hit L2 (re-read of the last row).
__global__ __launch_bounds__(NTHR) void seg_mean_pipe_kernel(
    const char* __restrict__ hs,   // [B, S, H] f32 as bytes
    const int*  __restrict__ wid,  // [B, S]
    char*       __restrict__ out)  // [B, NUM_WORDS, H] f32 as bytes
{
    __shared__ int   sm[W_PB + 1];
    __shared__ float4 buf[STAGES][NTHR];

    const int b  = blockIdx.y;
    const int w0 = blockIdx.x * W_PB;
    const int c  = threadIdx.x;

    if (c <= W_PB) {
        const int* __restrict__ row = wid + (size_t)b * S_DIM;
        const int target = w0 + c;
        int lo = 1, hi = S_DIM - 1;           // search [1, S-1)
        while (lo < hi) {
            int mid = (lo + hi) >> 1;
            if (__ldg(row + mid) < target) lo = mid + 1; else hi = mid;
        }
        sm[c] = lo;
    }
    __syncthreads();

    const int t0   = sm[0];
    const int tEnd = sm[W_PB];
    const int last = tEnd - 1;                // >= 0 always (t0 >= 1)

    const char* __restrict__ base =
        hs + (size_t)b * S_DIM * ROW_BYTES + c * 16;
    char* __restrict__ ob =
        out + ((size_t)b * NUM_WORDS + w0) * ROW_BYTES + c * 16;

    // Prologue: fill all stages (clamped issues are never consumed).
#pragma unroll
    for (int j = 0; j < STAGES; ++j) {
        const int tt = min(t0 + j, last);
        unsigned int dst = (unsigned int)__cvta_generic_to_shared(&buf[j][c]);
        asm volatile("cp.async.cg.shared.global [%0], [%1], 16;"
                     :: "r"(dst), "l"(base + (long)tt * ROW_BYTES) : "memory");
        asm volatile("cp.async.commit_group;" ::: "memory");
    }

    int t = t0;
    int ring = 0;
#pragma unroll 1
    for (int i = 0; i < W_PB; ++i) {
        const int e   = sm[i + 1];
        const int cnt = e - t;

        float4 acc = make_float4(0.f, 0.f, 0.f, 0.f);
#pragma unroll 1
        while (t < e) {
            // Oldest outstanding group (stage `ring`) is complete.
            asm volatile("cp.async.wait_group %0;" :: "n"(STAGES - 1) : "memory");
            float4 v = buf[ring][c];
            acc.x += v.x; acc.y += v.y; acc.z += v.z; acc.w += v.w;
            // Refill this stage with token t+STAGES (clamped tail -> unused).
            const int tt = min(t + STAGES, last);
            unsigned int dst =
                (unsigned int)__cvta_generic_to_shared(&buf[ring][c]);
            asm volatile("cp.async.cg.shared.global [%0], [%1], 16;"
                         :: "r"(dst), "l"(base + (long)tt * ROW_BYTES)
                         : "memory");
            asm volatile("cp.async.commit_group;" ::: "memory");
            ++t;
            if (++ring == STAGES) ring = 0;
        }

        const float inv = (cnt > 0) ? (1.0f / (float)cnt) : 0.0f;
        float4 r;
        r.x = acc.x * inv; r.y = acc.y * inv;
        r.z = acc.z * inv; r.w = acc.w * inv;
        __stcs((float4*)(ob + (long)i * ROW_BYTES), r);
    }
}

extern "C" void kernel_launch(void* const* d_in, const int* in_sizes, int n_in,
                              void* d_out, int out_size)
{
    const char* hs  = (const char*)d_in[0];   // hidden_states [B,S,H] f32
    const int*  wid = (const int*)d_in[1];    // word_ids [B,S] i32
    char*       out = (char*)d_out;           // [B, NUM_WORDS, H] f32

    dim3 grid(NUM_WORDS / W_PB, B_DIM);
    seg_mean_pipe_kernel<<<grid, NTHR>>>(hs, wid, out);
}

// round 13
// speedup vs baseline: 1.2455x; 1.0640x over previous
#include <cuda_runtime.h>
#include <cstdint>

// Problem constants (fixed by the reference)
#define B_DIM 16
#define S_DIM 4096
#define H_DIM 768
#define NUM_WORDS 2048            // S/2
#define ROW_BYTES (H_DIM * 4)     // 3072 bytes per token/word row
#define NTHR 192                  // one 16B chunk per thread per row
#define W_PB 8                    // words per block
#define STAGES 8                  // cp.async pipeline depth (power of 2)

// One block per (8 contiguous words, batch); grid 256 x 16 = 4096 blocks.
//
// word_ids[b, 1..S-2] is non-decreasing, contiguous 0..maxw (cumsum);
// positions 0 and S-1 are -1 (CLS/SEP, dropped). Threads c<=8 binary-search
// the start token of words w0..w0+8; for w > maxw lower_bound == S-1, so
// absent words get cnt=0 -> zero rows (matches reference).
//
// The 8 words cover ONE contiguous token range [t0, tEnd). Tokens stream
// through an 8-stage per-thread cp.async smem ring (128B in flight/thread,
// issue decoupled from the accumulate chain, continuous across word
// boundaries). Out-of-range refills use cp.async src-size=0 (zero-fill, NO
// memory transaction) — this removes the redundant tail traffic that capped
// round 12 (L2% ~= DRAM%). Stage reuse is same-thread only, so no
// __syncthreads in the mainloop.
__global__ __launch_bounds__(NTHR) void seg_mean_pipe_kernel(
    const char* __restrict__ hs,   // [B, S, H] f32 as bytes
    const int*  __restrict__ wid,  // [B, S]
    char*       __restrict__ out)  // [B, NUM_WORDS, H] f32 as bytes
{
    __shared__ int    sm[W_PB + 1];
    __shared__ float4 buf[STAGES][NTHR];

    const int b  = blockIdx.y;
    const int w0 = blockIdx.x * W_PB;
    const int c  = threadIdx.x;

    if (c <= W_PB) {
        const int* __restrict__ row = wid + (size_t)b * S_DIM;
        const int target = w0 + c;
        int lo = 1, hi = S_DIM - 1;           // search [1, S-1)
        while (lo < hi) {
            int mid = (lo + hi) >> 1;
            if (__ldg(row + mid) < target) lo = mid + 1; else hi = mid;
        }
        sm[c] = lo;
    }
    __syncthreads();

    const int t0   = sm[0];
    const int tEnd = sm[W_PB];
    const int last = tEnd - 1;                // last in-range token index

    const char* __restrict__ base =
        hs + (size_t)b * S_DIM * ROW_BYTES + c * 16;
    char* __restrict__ ob =
        out + ((size_t)b * NUM_WORDS + w0) * ROW_BYTES + c * 16;

    // Prologue: fill all stages. Out-of-range -> src-size 0 (zero-fill, no
    // transaction); address clamped to stay valid.
#pragma unroll
    for (int j = 0; j < STAGES; ++j) {
        const int tt = t0 + j;
        const int sz = (tt <= last) ? 16 : 0;
        const long off = (long)min(tt, max(last, 1)) * ROW_BYTES;
        unsigned int dst = (unsigned int)__cvta_generic_to_shared(&buf[j][c]);
        asm volatile("cp.async.cg.shared.global [%0], [%1], 16, %2;"
                     :: "r"(dst), "l"(base + off), "r"(sz) : "memory");
        asm volatile("cp.async.commit_group;" ::: "memory");
    }

    int t = t0;
    int ring = 0;
#pragma unroll 1
    for (int i = 0; i < W_PB; ++i) {
        const int e   = sm[i + 1];
        const int cnt = e - t;

        float4 acc = make_float4(0.f, 0.f, 0.f, 0.f);
#pragma unroll 1
        while (t < e) {
            // Oldest outstanding group (stage `ring`) is complete.
            asm volatile("cp.async.wait_group %0;" :: "n"(STAGES - 1)
                         : "memory");
            float4 v = buf[ring][c];
            acc.x += v.x; acc.y += v.y; acc.z += v.z; acc.w += v.w;
            // Refill this stage with token t+STAGES (zero-fill if past end).
            const int tt = t + STAGES;
            const int sz = (tt <= last) ? 16 : 0;
            const long off = (long)min(tt, last) * ROW_BYTES;
            unsigned int dst =
                (unsigned int)__cvta_generic_to_shared(&buf[ring][c]);
            asm volatile("cp.async.cg.shared.global [%0], [%1], 16, %2;"
                         :: "r"(dst), "l"(base + off), "r"(sz) : "memory");
            asm volatile("cp.async.commit_group;" ::: "memory");
            ++t;
            ring = (ring + 1) & (STAGES - 1);
        }

        const float inv = (cnt > 0) ? (1.0f / (float)cnt) : 0.0f;
        float4 r;
        r.x = acc.x * inv; r.y = acc.y * inv;
        r.z = acc.z * inv; r.w = acc.w * inv;
        __stcs((float4*)(ob + (long)i * ROW_BYTES), r);
    }
}

extern "C" void kernel_launch(void* const* d_in, const int* in_sizes, int n_in,
                              void* d_out, int out_size)
{
    const char* hs  = (const char*)d_in[0];   // hidden_states [B,S,H] f32
    const int*  wid = (const int*)d_in[1];    // word_ids [B,S] i32
    char*       out = (char*)d_out;           // [B, NUM_WORDS, H] f32

    dim3 grid(NUM_WORDS / W_PB, B_DIM);
    seg_mean_pipe_kernel<<<grid, NTHR>>>(hs, wid, out);
}

// round 14
// speedup vs baseline: 1.2632x; 1.0142x over previous
#include <cuda_runtime.h>
#include <cstdint>

// Problem constants (fixed by the reference)
#define B_DIM 16
#define S_DIM 4096
#define H_DIM 768
#define NUM_WORDS 2048            // S/2
#define ROW_BYTES (H_DIM * 4)     // 3072 bytes per token/word row
#define NTHR 192                  // one 16B chunk per thread per row
#define W_PB 8                    // words per block
#define STAGES 8                  // cp.async pipeline depth (power of 2)

// Scratch: word start-token table, [B][NUM_WORDS+1].
// Word ids are contiguous 0..maxw (cumsum construction): starts[b][w] = first
// token of word w; starts[b][maxw+1] = S-1 (sentinel; token S-1 is SEP=-1).
// Entries past maxw+1 stay 0 (zero-initialized device globals; every call
// performs identical writes -> deterministic across graph replays). The main
// kernel monotone-repairs its 9-entry window (running max), so stale zeros
// become empty words (cnt=0 -> zero rows), matching the reference.
__device__ int g_starts[B_DIM * (NUM_WORDS + 1)];

// One thread per token: mark segment starts + write sentinel. (~1MB read)
__global__ void scatter_starts_kernel(const int* __restrict__ wid) {
    const int b = blockIdx.y;
    const int t = blockIdx.x * blockDim.x + threadIdx.x;
    const int* row = wid + (size_t)b * S_DIM;
    if (t >= 1 && t < S_DIM - 1) {
        int w = row[t];
        if (w >= 0 && row[t - 1] != w) {
            g_starts[b * (NUM_WORDS + 1) + w] = t;
        }
    } else if (t == S_DIM - 1) {
        int maxw = row[S_DIM - 2];           // last valid word id
        g_starts[b * (NUM_WORDS + 1) + maxw + 1] = S_DIM - 1;
    }
}

// One block per (8 contiguous words, batch); grid 256 x 16 = 4096 blocks.
// The 8 words cover ONE contiguous token range [t0, tEnd). Tokens stream
// through an 8-stage per-thread cp.async smem ring (128B in flight/thread,
// issue decoupled from the accumulate chain, continuous across word
// boundaries). Out-of-range refills use cp.async src-size=0 (zero-fill, no
// memory transaction). Prefetch addresses advance by a running pointer (no
// per-iteration 64-bit multiply). No in-block binary search: boundaries come
// from g_starts, so the per-block serial prologue that capped round 13 is
// gone.
__global__ __launch_bounds__(NTHR) void seg_mean_pipe_kernel(
    const char* __restrict__ hs,   // [B, S, H] f32 as bytes
    char*       __restrict__ out)  // [B, NUM_WORDS, H] f32 as bytes
{
    __shared__ int    sm[W_PB + 1];
    __shared__ float4 buf[STAGES][NTHR];

    const int b  = blockIdx.y;
    const int w0 = blockIdx.x * W_PB;
    const int c  = threadIdx.x;

    if (c <= W_PB) sm[c] = g_starts[b * (NUM_WORDS + 1) + w0 + c];
    __syncthreads();
    if (c == 0) {
        int run = sm[0];
#pragma unroll
        for (int i = 1; i <= W_PB; ++i) {
            run = max(run, sm[i]);
            sm[i] = run;
        }
    }
    __syncthreads();

    const int t0   = sm[0];
    const int tEnd = sm[W_PB];
    const int last = tEnd - 1;                // last in-range token index

    const char* __restrict__ base =
        hs + (size_t)b * S_DIM * ROW_BYTES + c * 16;
    char* __restrict__ ob =
        out + ((size_t)b * NUM_WORDS + w0) * ROW_BYTES + c * 16;

    // Running prefetch pointer (never dereferenced when out of range).
    const char* pf = base + (long)t0 * ROW_BYTES;

    // Prologue: fill all stages; out-of-range -> src-size 0 (zero-fill).
#pragma unroll
    for (int j = 0; j < STAGES; ++j) {
        const bool ok = (t0 + j) <= last;
        const char* src = ok ? pf : base;
        const int sz = ok ? 16 : 0;
        unsigned int dst = (unsigned int)__cvta_generic_to_shared(&buf[j][c]);
        asm volatile("cp.async.cg.shared.global [%0], [%1], 16, %2;"
                     :: "r"(dst), "l"(src), "r"(sz) : "memory");
        asm volatile("cp.async.commit_group;" ::: "memory");
        pf += ROW_BYTES;
    }

    int t = t0;
    int ring = 0;
#pragma unroll 1
    for (int i = 0; i < W_PB; ++i) {
        const int e   = sm[i + 1];
        const int cnt = e - t;

        float4 acc = make_float4(0.f, 0.f, 0.f, 0.f);
#pragma unroll 1
        while (t < e) {
            // Oldest outstanding group (stage `ring`) is complete.
            asm volatile("cp.async.wait_group %0;" :: "n"(STAGES - 1)
                         : "memory");
            float4 v = buf[ring][c];
            acc.x += v.x; acc.y += v.y; acc.z += v.z; acc.w += v.w;
            // Refill this stage with token t+STAGES (zero-fill past end).
            const bool ok = (t + STAGES) <= last;
            const char* src = ok ? pf : base;
            const int sz = ok ? 16 : 0;
            unsigned int dst =
                (unsigned int)__cvta_generic_to_shared(&buf[ring][c]);
            asm volatile("cp.async.cg.shared.global [%0], [%1], 16, %2;"
                         :: "r"(dst), "l"(src), "r"(sz) : "memory");
            asm volatile("cp.async.commit_group;" ::: "memory");
            pf += ROW_BYTES;
            ++t;
            ring = (ring + 1) & (STAGES - 1);
        }

        const float inv = (cnt > 0) ? (1.0f / (float)cnt) : 0.0f;
        float4 r;
        r.x = acc.x * inv; r.y = acc.y * inv;
        r.z = acc.z * inv; r.w = acc.w * inv;
        __stcs((float4*)(ob + (long)i * ROW_BYTES), r);
    }
}

extern "C" void kernel_launch(void* const* d_in, const int* in_sizes, int n_in,
                              void* d_out, int out_size)
{
    const char* hs  = (const char*)d_in[0];   // hidden_states [B,S,H] f32
    const int*  wid = (const int*)d_in[1];    // word_ids [B,S] i32
    char*       out = (char*)d_out;           // [B, NUM_WORDS, H] f32

    {
        dim3 grid(S_DIM / 256, B_DIM);
        scatter_starts_kernel<<<grid, 256>>>(wid);
    }
    {
        dim3 grid(NUM_WORDS / W_PB, B_DIM);
        seg_mean_pipe_kernel<<<grid, NTHR>>>(hs, out);
    }
}